// round 11
// baseline (speedup 1.0000x reference)
#include <cuda_runtime.h>
#include <cuda_fp16.h>

// LogicConv3d: B=16, C=3, H=W=32, K=64, P=784, S=64, 7-level soft logic tree.
// d_in: [0]=x f32[16,3,32,32], [1..7]=w0..w6 f32[2^(6-l),64,16],
//       [8]=left_idx i32[64,784,64,3], [9]=right_idx i32[64,784,64,3]
// d_out: f32[16,64,784,1]

#define B_ 16
#define C_ 3
#define HW_ 1024
#define CHW_ 3072
#define K_ 64
#define P_ 784
#define KP_ (K_ * P_)     // 50176
#define NROWS 127
#define TP 16             // patches per block (784 = 49*16)

// scratch
__device__ float4 g_coef[K_ * NROWS];     // per-(k,node) gate coeffs (fp32)
__device__ uint4  g_coefh[K_ * NROWS];    // same, splatted half2 {c0c0,c1c1,c2c2,c3c3}
__device__ __half g_xth[CHW_ * B_];       // x transposed fp16: [offset][batch] (96KB)

__constant__ float G4[16][4] = {
    {0,0,0,0},{0,0,0,1},{0,1,0,-1},{0,1,0,0},
    {0,0,1,-1},{0,0,1,0},{0,1,1,-2},{0,1,1,-1},
    {1,-1,-1,1},{1,-1,-1,2},{1,0,-1,0},{1,0,-1,1},
    {1,-1,0,0},{1,-1,0,1},{1,0,0,-1},{1,0,0,0}};

// ---------------------------------------------------------------------------
// Prep (tiny): softmax coeffs (fp32 + half2-splat) + fp16 x transpose.
// ---------------------------------------------------------------------------
__global__ void prep_kernel(const float* __restrict__ x,
                            const float* __restrict__ w0, const float* __restrict__ w1,
                            const float* __restrict__ w2, const float* __restrict__ w3,
                            const float* __restrict__ w4, const float* __restrict__ w5,
                            const float* __restrict__ w6) {
    int r = blockIdx.x * 256 + threadIdx.x;
    if (r < NROWS * K_) {
        int row = r >> 6;
        int k   = r & 63;
        int bse = 0, n = 64, l = 0;
        while (row >= bse + n) { bse += n; n >>= 1; ++l; }
        int s = row - bse;
        const float* ws[7] = {w0, w1, w2, w3, w4, w5, w6};
        const float* p = ws[l] + (s * K_ + k) * 16;
        float v[16], m = -1e30f;
#pragma unroll
        for (int i = 0; i < 16; ++i) { v[i] = p[i]; m = fmaxf(m, v[i]); }
        float sum = 0.f, c0 = 0.f, c1 = 0.f, c2 = 0.f, c3 = 0.f;
#pragma unroll
        for (int i = 0; i < 16; ++i) {
            float e = expf(v[i] - m);
            sum += e;
            c0 += e * G4[i][0]; c1 += e * G4[i][1];
            c2 += e * G4[i][2]; c3 += e * G4[i][3];
        }
        float inv = 1.f / sum;
        c0 *= inv; c1 *= inv; c2 *= inv; c3 *= inv;
        g_coef[k * NROWS + row] = make_float4(c0, c1, c2, c3);
        union { __half2 h[4]; uint4 u; } cv;
        cv.h[0] = __float2half2_rn(c0); cv.h[1] = __float2half2_rn(c1);
        cv.h[2] = __float2half2_rn(c2); cv.h[3] = __float2half2_rn(c3);
        g_coefh[k * NROWS + row] = cv.u;
        return;
    }
    r -= NROWS * K_;
    if (r < CHW_ * B_) {
        int b = r & 15, off = r >> 4;
        g_xth[r] = __float2half(x[b * CHW_ + off]);
    }
}

// ---------------------------------------------------------------------------
// Main kernel: 128 threads = 8 batch-pairs x 16 patches, one k.
// Breadth-first evaluation of four 16-leaf subtrees in half2 (HFMA2), then
// the final 3 nodes in fp32. Per subtree: 16 leaf gates (32 gathers issued
// as a flat run -> high MLP), then explicit 8/4/2/1 merge levels with
// closed-form node indices (level-l base = 128 - (128>>l)).
// ---------------------------------------------------------------------------
__device__ __forceinline__ __half2 hgate(__half2 a, __half2 b, uint4 cw) {
    const __half2* c = (const __half2*)&cw;
    // c0 + c1*a + c2*b + c3*a*b
    return __hfma2(b, __hfma2(c[3], a, c[2]), __hfma2(c[1], a, c[0]));
}

__device__ __forceinline__ float2 gate2(float2 a, float2 b, float4 c) {
    float2 r;
    r.x = fmaf(b.x, fmaf(c.w, a.x, c.z), fmaf(c.y, a.x, c.x));
    r.y = fmaf(b.y, fmaf(c.w, a.y, c.z), fmaf(c.y, a.y, c.x));
    return r;
}

__global__ __launch_bounds__(128, 10)
void logic_kernel(const int* __restrict__ lidx,
                  const int* __restrict__ ridx,
                  float* __restrict__ out) {
    __shared__ int2  soff[TP][65];     // [patch][s] = (left,right) BYTE offsets into fp16 xt
    __shared__ uint4 scoefh[NROWS];    // half2-splatted coeffs, 16B/node

    const int k   = blockIdx.y;
    const int p0  = blockIdx.x * TP;
    const int tid = threadIdx.x;

    if (tid < NROWS) scoefh[tid] = g_coefh[k * NROWS + tid];

    // decode idx triples -> byte offsets (row*32), coalesced, shared across b
    {
        const int* lb = lidx + (k * P_ + p0) * (64 * 3);
        const int* rb = ridx + (k * P_ + p0) * (64 * 3);
#pragma unroll
        for (int e = tid; e < TP * 64; e += 128) {
            int pl = e >> 6, s = e & 63;
            int h = lb[3 * e], w = lb[3 * e + 1], c = lb[3 * e + 2];
            int lo = (c * HW_ + h * 32 + w) << 5;
            h = rb[3 * e]; w = rb[3 * e + 1]; c = rb[3 * e + 2];
            int ro = (c * HW_ + h * 32 + w) << 5;
            soff[pl][s] = make_int2(lo, ro);
        }
    }
    __syncthreads();

    const int bg2 = tid & 7;           // batch pair (2 batches, half2)
    const int pl  = tid >> 3;          // patch lane 0..15 (consecutive in warp)
    const char* xtb = (const char*)g_xth + bg2 * 4;

    float2 lv4[4];                     // the 4 level-4 subtree outputs (fp32)
#pragma unroll
    for (int g = 0; g < 4; ++g) {
        __half2 v[16];
        // leaves: 32 gathers + 16 gates
#pragma unroll
        for (int t = 0; t < 16; ++t) {
            const int s = (g << 4) + t;
            int2 o = soff[pl][s];
            __half2 A  = *(const __half2*)(xtb + o.x);
            __half2 Bv = *(const __half2*)(xtb + o.y);
            v[t] = hgate(A, Bv, scoefh[s]);
        }
        // level 1: nodes 64 + 8g + t
#pragma unroll
        for (int t = 0; t < 8; ++t)
            v[t] = hgate(v[2 * t], v[2 * t + 1], scoefh[64 + (g << 3) + t]);
        // level 2: nodes 96 + 4g + t
#pragma unroll
        for (int t = 0; t < 4; ++t)
            v[t] = hgate(v[2 * t], v[2 * t + 1], scoefh[96 + (g << 2) + t]);
        // level 3: nodes 112 + 2g + t
#pragma unroll
        for (int t = 0; t < 2; ++t)
            v[t] = hgate(v[2 * t], v[2 * t + 1], scoefh[112 + (g << 1) + t]);
        // level 4: node 120 + g
        lv4[g] = __half22float2(hgate(v[0], v[1], scoefh[120 + g]));
    }

    // last two levels in fp32 (coeffs uniform across block -> cached LDG)
    const float4* gcf = g_coef + k * NROWS;
    float2 t5a = gate2(lv4[0], lv4[1], gcf[124]);
    float2 t5b = gate2(lv4[2], lv4[3], gcf[125]);
    float2 r   = gate2(t5a, t5b, gcf[126]);

    long ob0 = (long)(bg2 * 2) * KP_ + k * P_ + p0 + pl;
    out[ob0]       = r.x;
    out[ob0 + KP_] = r.y;
}

// ---------------------------------------------------------------------------
extern "C" void kernel_launch(void* const* d_in, const int* in_sizes, int n_in,
                              void* d_out, int out_size) {
    const float* x  = (const float*)d_in[0];
    const float* w0 = (const float*)d_in[1];
    const float* w1 = (const float*)d_in[2];
    const float* w2 = (const float*)d_in[3];
    const float* w3 = (const float*)d_in[4];
    const float* w4 = (const float*)d_in[5];
    const float* w5 = (const float*)d_in[6];
    const float* w6 = (const float*)d_in[7];
    const int* lidx = (const int*)d_in[8];
    const int* ridx = (const int*)d_in[9];
    float* out = (float*)d_out;

    int prep_work = NROWS * K_ + CHW_ * B_;           // 57280
    prep_kernel<<<(prep_work + 255) / 256, 256>>>(x, w0, w1, w2, w3, w4, w5, w6);
    logic_kernel<<<dim3(P_ / TP, K_), 128>>>(lidx, ridx, out);
}

// round 12
// speedup vs baseline: 1.0253x; 1.0253x over previous
#include <cuda_runtime.h>
#include <cuda_fp16.h>

// LogicConv3d: B=16, C=3, H=W=32, K=64, P=784, S=64, 7-level soft logic tree.
// d_in: [0]=x f32[16,3,32,32], [1..7]=w0..w6 f32[2^(6-l),64,16],
//       [8]=left_idx i32[64,784,64,3], [9]=right_idx i32[64,784,64,3]
// d_out: f32[16,64,784,1]

#define B_ 16
#define C_ 3
#define HW_ 1024
#define CHW_ 3072
#define K_ 64
#define P_ 784
#define KP_ (K_ * P_)     // 50176
#define NROWS 127
#define TP 16             // patches per block (784 = 49*16)

// scratch
__device__ float4 g_coef[K_ * NROWS];     // per-(k,node) gate coeffs (fp32)
__device__ uint4  g_coefh[K_ * NROWS];    // same, splatted half2 {c0c0,c1c1,c2c2,c3c3}
__device__ __half g_xth[CHW_ * B_];       // x transposed fp16: [offset][batch] (96KB)

__constant__ float G4[16][4] = {
    {0,0,0,0},{0,0,0,1},{0,1,0,-1},{0,1,0,0},
    {0,0,1,-1},{0,0,1,0},{0,1,1,-2},{0,1,1,-1},
    {1,-1,-1,1},{1,-1,-1,2},{1,0,-1,0},{1,0,-1,1},
    {1,-1,0,0},{1,-1,0,1},{1,0,0,-1},{1,0,0,0}};

// ---------------------------------------------------------------------------
// Prep (tiny): softmax coeffs (fp32 + half2-splat) + fp16 x transpose.
// ---------------------------------------------------------------------------
__global__ void prep_kernel(const float* __restrict__ x,
                            const float* __restrict__ w0, const float* __restrict__ w1,
                            const float* __restrict__ w2, const float* __restrict__ w3,
                            const float* __restrict__ w4, const float* __restrict__ w5,
                            const float* __restrict__ w6) {
    int r = blockIdx.x * 256 + threadIdx.x;
    if (r < NROWS * K_) {
        int row = r >> 6;
        int k   = r & 63;
        int bse = 0, n = 64, l = 0;
        while (row >= bse + n) { bse += n; n >>= 1; ++l; }
        int s = row - bse;
        const float* ws[7] = {w0, w1, w2, w3, w4, w5, w6};
        const float* p = ws[l] + (s * K_ + k) * 16;
        float v[16], m = -1e30f;
#pragma unroll
        for (int i = 0; i < 16; ++i) { v[i] = p[i]; m = fmaxf(m, v[i]); }
        float sum = 0.f, c0 = 0.f, c1 = 0.f, c2 = 0.f, c3 = 0.f;
#pragma unroll
        for (int i = 0; i < 16; ++i) {
            float e = expf(v[i] - m);
            sum += e;
            c0 += e * G4[i][0]; c1 += e * G4[i][1];
            c2 += e * G4[i][2]; c3 += e * G4[i][3];
        }
        float inv = 1.f / sum;
        c0 *= inv; c1 *= inv; c2 *= inv; c3 *= inv;
        g_coef[k * NROWS + row] = make_float4(c0, c1, c2, c3);
        union { __half2 h[4]; uint4 u; } cv;
        cv.h[0] = __float2half2_rn(c0); cv.h[1] = __float2half2_rn(c1);
        cv.h[2] = __float2half2_rn(c2); cv.h[3] = __float2half2_rn(c3);
        g_coefh[k * NROWS + row] = cv.u;
        return;
    }
    r -= NROWS * K_;
    if (r < CHW_ * B_) {
        int b = r & 15, off = r >> 4;
        g_xth[r] = __float2half(x[b * CHW_ + off]);
    }
}

// ---------------------------------------------------------------------------
// Main kernel: 64 threads = 4 batch-quads x 16 patches, one k.
// Each thread carries 4 batches as two half2 (one LDG.64 per gather side).
// Per-warp L1 traffic (soff LDS, coef LDS, idx decode) is amortized over
// 2x the values of the previous layout. soff packed 2 s-steps per LDS.128.
// Tree levels 0-4 in HFMA2, last two levels fp32.
// ---------------------------------------------------------------------------
struct h2x2 { __half2 a, b; };

__device__ __forceinline__ h2x2 hgate2(h2x2 A, h2x2 B, uint4 cw) {
    const __half2* c = (const __half2*)&cw;
    h2x2 r;
    r.a = __hfma2(B.a, __hfma2(c[3], A.a, c[2]), __hfma2(c[1], A.a, c[0]));
    r.b = __hfma2(B.b, __hfma2(c[3], A.b, c[2]), __hfma2(c[1], A.b, c[0]));
    return r;
}

__device__ __forceinline__ float2 gate2(float2 a, float2 b, float4 c) {
    float2 r;
    r.x = fmaf(b.x, fmaf(c.w, a.x, c.z), fmaf(c.y, a.x, c.x));
    r.y = fmaf(b.y, fmaf(c.w, a.y, c.z), fmaf(c.y, a.y, c.x));
    return r;
}

__global__ __launch_bounds__(64, 16)
void logic_kernel(const int* __restrict__ lidx,
                  const int* __restrict__ ridx,
                  float* __restrict__ out) {
    __shared__ int2  soff[TP][66];     // [patch][s]=(l,r) BYTE offsets; stride 528B (16B-aligned)
    __shared__ uint4 scoefh[NROWS];    // half2-splatted coeffs, 16B/node

    const int k   = blockIdx.y;
    const int p0  = blockIdx.x * TP;
    const int tid = threadIdx.x;

    for (int i = tid; i < NROWS; i += 64) scoefh[i] = g_coefh[k * NROWS + i];

    // decode idx triples -> byte offsets (row*32), coalesced, shared across b
    {
        const int* lb = lidx + (k * P_ + p0) * (64 * 3);
        const int* rb = ridx + (k * P_ + p0) * (64 * 3);
#pragma unroll
        for (int e = tid; e < TP * 64; e += 64) {
            int pl = e >> 6, s = e & 63;
            int h = lb[3 * e], w = lb[3 * e + 1], c = lb[3 * e + 2];
            int lo = (c * HW_ + h * 32 + w) << 5;
            h = rb[3 * e]; w = rb[3 * e + 1]; c = rb[3 * e + 2];
            int ro = (c * HW_ + h * 32 + w) << 5;
            soff[pl][s] = make_int2(lo, ro);
        }
    }
    __syncthreads();

    const int bg4 = tid & 3;           // batch quad (4 batches = 2 half2 = 8B)
    const int pl  = tid >> 2;          // patch lane 0..15 (8 consecutive per warp)
    const char* xtb = (const char*)g_xth + bg4 * 8;

    float2 lv4a[4], lv4b[4];           // level-4 subtree outputs (fp32, 4 batches)
#pragma unroll
    for (int g = 0; g < 4; ++g) {
        h2x2 v[16];
        // leaves: 2 s-steps per int4 offset load; 4 LDG.64 gathers each
#pragma unroll
        for (int t = 0; t < 16; t += 2) {
            const int s = (g << 4) + t;
            int4 oo = *(const int4*)&soff[pl][s];
            h2x2 A0 = *(const h2x2*)(xtb + oo.x);
            h2x2 B0 = *(const h2x2*)(xtb + oo.y);
            h2x2 A1 = *(const h2x2*)(xtb + oo.z);
            h2x2 B1 = *(const h2x2*)(xtb + oo.w);
            v[t]     = hgate2(A0, B0, scoefh[s]);
            v[t + 1] = hgate2(A1, B1, scoefh[s + 1]);
        }
        // level 1: nodes 64 + 8g + t
#pragma unroll
        for (int t = 0; t < 8; ++t)
            v[t] = hgate2(v[2 * t], v[2 * t + 1], scoefh[64 + (g << 3) + t]);
        // level 2: nodes 96 + 4g + t
#pragma unroll
        for (int t = 0; t < 4; ++t)
            v[t] = hgate2(v[2 * t], v[2 * t + 1], scoefh[96 + (g << 2) + t]);
        // level 3: nodes 112 + 2g + t
#pragma unroll
        for (int t = 0; t < 2; ++t)
            v[t] = hgate2(v[2 * t], v[2 * t + 1], scoefh[112 + (g << 1) + t]);
        // level 4: node 120 + g
        h2x2 r4 = hgate2(v[0], v[1], scoefh[120 + g]);
        lv4a[g] = __half22float2(r4.a);
        lv4b[g] = __half22float2(r4.b);
    }

    // last two levels in fp32 (coeffs uniform across block -> cached LDG)
    const float4* gcf = g_coef + k * NROWS;
    float4 c5a = gcf[124], c5b = gcf[125], c6 = gcf[126];
    float2 ta = gate2(gate2(lv4a[0], lv4a[1], c5a), gate2(lv4a[2], lv4a[3], c5b), c6);
    float2 tb = gate2(gate2(lv4b[0], lv4b[1], c5a), gate2(lv4b[2], lv4b[3], c5b), c6);

    long ob0 = (long)(bg4 * 4) * KP_ + k * P_ + p0 + pl;
    out[ob0]           = ta.x;
    out[ob0 + KP_]     = ta.y;
    out[ob0 + 2 * KP_] = tb.x;
    out[ob0 + 3 * KP_] = tb.y;
}

// ---------------------------------------------------------------------------
extern "C" void kernel_launch(void* const* d_in, const int* in_sizes, int n_in,
                              void* d_out, int out_size) {
    const float* x  = (const float*)d_in[0];
    const float* w0 = (const float*)d_in[1];
    const float* w1 = (const float*)d_in[2];
    const float* w2 = (const float*)d_in[3];
    const float* w3 = (const float*)d_in[4];
    const float* w4 = (const float*)d_in[5];
    const float* w5 = (const float*)d_in[6];
    const float* w6 = (const float*)d_in[7];
    const int* lidx = (const int*)d_in[8];
    const int* ridx = (const int*)d_in[9];
    float* out = (float*)d_out;

    int prep_work = NROWS * K_ + CHW_ * B_;           // 57280
    prep_kernel<<<(prep_work + 255) / 256, 256>>>(x, w0, w1, w2, w3, w4, w5, w6);
    logic_kernel<<<dim3(P_ / TP, K_), 64>>>(lidx, ridx, out);
}

// round 14
// speedup vs baseline: 1.1548x; 1.1263x over previous
#include <cuda_runtime.h>
#include <cuda_fp16.h>

// LogicConv3d: B=16, C=3, H=W=32, K=64, P=784, S=64, 7-level soft logic tree.
// d_in: [0]=x f32[16,3,32,32], [1..7]=w0..w6 f32[2^(6-l),64,16],
//       [8]=left_idx i32[64,784,64,3], [9]=right_idx i32[64,784,64,3]
// d_out: f32[16,64,784,1]
//
// KEY STRUCTURE: idx(k,p,s) = idx(k,0,s) + patch_shift(p), where
// shift(p) = (p/28)*32 + (p%28) in flat (c*1024+h*32+w) space (exact:
// h = hb + ih with hb<5, ih<28 -> h<32, no carry; same for w). So the
// 77MB idx tensors reduce to their 196KB p=0 slice.

#define B_ 16
#define C_ 3
#define HW_ 1024
#define CHW_ 3072
#define K_ 64
#define P_ 784
#define KP_ (K_ * P_)     // 50176
#define NROWS 127
#define TP 16             // patches per block (784 = 49*16)

// scratch
__device__ float4 g_coef[K_ * NROWS];     // per-(k,node) gate coeffs (fp32)
__device__ uint4  g_coefh[K_ * NROWS];    // same, splatted half2 {c0c0,c1c1,c2c2,c3c3}
__device__ __half g_xth[CHW_ * B_];       // x transposed fp16: [row][batch] (96KB)
__device__ int2   g_off0[K_ * 64];        // p=0 (left,right) BYTE offsets per (k,s)

__constant__ float G4[16][4] = {
    {0,0,0,0},{0,0,0,1},{0,1,0,-1},{0,1,0,0},
    {0,0,1,-1},{0,0,1,0},{0,1,1,-2},{0,1,1,-1},
    {1,-1,-1,1},{1,-1,-1,2},{1,0,-1,0},{1,0,-1,1},
    {1,-1,0,0},{1,-1,0,1},{1,0,0,-1},{1,0,0,0}};

// ---------------------------------------------------------------------------
// Prep (tiny): softmax coeffs + fp16 x transpose + p=0 offset extraction.
// ---------------------------------------------------------------------------
__global__ void prep_kernel(const float* __restrict__ x,
                            const float* __restrict__ w0, const float* __restrict__ w1,
                            const float* __restrict__ w2, const float* __restrict__ w3,
                            const float* __restrict__ w4, const float* __restrict__ w5,
                            const float* __restrict__ w6,
                            const int* __restrict__ lidx,
                            const int* __restrict__ ridx) {
    int r = blockIdx.x * 256 + threadIdx.x;
    if (r < NROWS * K_) {
        int row = r >> 6;
        int k   = r & 63;
        int bse = 0, n = 64, l = 0;
        while (row >= bse + n) { bse += n; n >>= 1; ++l; }
        int s = row - bse;
        const float* ws[7] = {w0, w1, w2, w3, w4, w5, w6};
        const float* p = ws[l] + (s * K_ + k) * 16;
        float v[16], m = -1e30f;
#pragma unroll
        for (int i = 0; i < 16; ++i) { v[i] = p[i]; m = fmaxf(m, v[i]); }
        float sum = 0.f, c0 = 0.f, c1 = 0.f, c2 = 0.f, c3 = 0.f;
#pragma unroll
        for (int i = 0; i < 16; ++i) {
            float e = expf(v[i] - m);
            sum += e;
            c0 += e * G4[i][0]; c1 += e * G4[i][1];
            c2 += e * G4[i][2]; c3 += e * G4[i][3];
        }
        float inv = 1.f / sum;
        c0 *= inv; c1 *= inv; c2 *= inv; c3 *= inv;
        g_coef[k * NROWS + row] = make_float4(c0, c1, c2, c3);
        union { __half2 h[4]; uint4 u; } cv;
        cv.h[0] = __float2half2_rn(c0); cv.h[1] = __float2half2_rn(c1);
        cv.h[2] = __float2half2_rn(c2); cv.h[3] = __float2half2_rn(c3);
        g_coefh[k * NROWS + row] = cv.u;
        return;
    }
    r -= NROWS * K_;
    if (r < CHW_ * B_) {
        int b = r & 15, off = r >> 4;
        g_xth[r] = __float2half(x[b * CHW_ + off]);
        return;
    }
    r -= CHW_ * B_;
    if (r < K_ * 64) {
        int k = r >> 6;
        int s = r & 63;
        long base = ((long)k * P_ * 64 + s) * 3;     // the p = 0 slice
        int h = lidx[base], w = lidx[base + 1], c = lidx[base + 2];
        int lo = (c * HW_ + h * 32 + w) << 5;        // byte offset into fp16 xt
        h = ridx[base]; w = ridx[base + 1]; c = ridx[base + 2];
        int ro = (c * HW_ + h * 32 + w) << 5;
        g_off0[r] = make_int2(lo, ro);
    }
}

// ---------------------------------------------------------------------------
// Main kernel: 128 threads = 8 batch-pairs x 16 patches, one k.
// The per-thread patch shift is folded into the gather base pointer; the
// s-loop reads base offsets from a 64-entry broadcast table (1 wavefront
// per LDS). No idx decode, no per-patch SMEM, no 77MB DRAM stream.
// Tree levels 0-4 in HFMA2 (breadth-first per 16-leaf group), last two fp32.
// ---------------------------------------------------------------------------
__device__ __forceinline__ __half2 hgate(__half2 a, __half2 b, uint4 cw) {
    const __half2* c = (const __half2*)&cw;
    return __hfma2(b, __hfma2(c[3], a, c[2]), __hfma2(c[1], a, c[0]));
}

__device__ __forceinline__ float2 gate2(float2 a, float2 b, float4 c) {
    float2 r;
    r.x = fmaf(b.x, fmaf(c.w, a.x, c.z), fmaf(c.y, a.x, c.x));
    r.y = fmaf(b.y, fmaf(c.w, a.y, c.z), fmaf(c.y, a.y, c.x));
    return r;
}

__global__ __launch_bounds__(128, 12)
void logic_kernel(float* __restrict__ out) {
    __shared__ uint4 scoefh[NROWS];    // half2-splatted coeffs, 16B/node
    __shared__ int2  soff0[64];        // p=0 (left,right) byte offsets (broadcast)

    const int k   = blockIdx.y;
    const int p0  = blockIdx.x * TP;
    const int tid = threadIdx.x;

    if (tid < NROWS) scoefh[tid] = g_coefh[k * NROWS + tid];
    if (tid < 64)    soff0[tid]  = g_off0[(k << 6) + tid];
    __syncthreads();

    const int bg2 = tid & 7;           // batch pair (2 batches, half2)
    const int pl  = tid >> 3;          // patch lane 0..15 (consecutive in warp)
    const int p   = p0 + pl;
    const int ih  = p / 28;
    const int iw  = p - ih * 28;
    // patch shift in bytes: (ih*32 + iw) rows * 32 B/row
    const char* xtb = (const char*)g_xth + bg2 * 4 + ih * 1024 + iw * 32;

    float2 lv4[4];                     // the 4 level-4 subtree outputs (fp32)
#pragma unroll
    for (int g = 0; g < 4; ++g) {
        __half2 v[16];
        // leaves: 32 gathers + 16 gates (base offsets broadcast from SMEM)
#pragma unroll
        for (int t = 0; t < 16; ++t) {
            const int s = (g << 4) + t;
            int2 o = soff0[s];
            __half2 A  = *(const __half2*)(xtb + o.x);
            __half2 Bv = *(const __half2*)(xtb + o.y);
            v[t] = hgate(A, Bv, scoefh[s]);
        }
        // level 1: nodes 64 + 8g + t
#pragma unroll
        for (int t = 0; t < 8; ++t)
            v[t] = hgate(v[2 * t], v[2 * t + 1], scoefh[64 + (g << 3) + t]);
        // level 2: nodes 96 + 4g + t
#pragma unroll
        for (int t = 0; t < 4; ++t)
            v[t] = hgate(v[2 * t], v[2 * t + 1], scoefh[96 + (g << 2) + t]);
        // level 3: nodes 112 + 2g + t
#pragma unroll
        for (int t = 0; t < 2; ++t)
            v[t] = hgate(v[2 * t], v[2 * t + 1], scoefh[112 + (g << 1) + t]);
        // level 4: node 120 + g
        lv4[g] = __half22float2(hgate(v[0], v[1], scoefh[120 + g]));
    }

    // last two levels in fp32 (coeffs uniform across block -> cached LDG)
    const float4* gcf = g_coef + k * NROWS;
    float2 t5a = gate2(lv4[0], lv4[1], gcf[124]);
    float2 t5b = gate2(lv4[2], lv4[3], gcf[125]);
    float2 r   = gate2(t5a, t5b, gcf[126]);

    long ob0 = (long)(bg2 * 2) * KP_ + k * P_ + p;
    out[ob0]       = r.x;
    out[ob0 + KP_] = r.y;
}

// ---------------------------------------------------------------------------
extern "C" void kernel_launch(void* const* d_in, const int* in_sizes, int n_in,
                              void* d_out, int out_size) {
    const float* x  = (const float*)d_in[0];
    const float* w0 = (const float*)d_in[1];
    const float* w1 = (const float*)d_in[2];
    const float* w2 = (const float*)d_in[3];
    const float* w3 = (const float*)d_in[4];
    const float* w4 = (const float*)d_in[5];
    const float* w5 = (const float*)d_in[6];
    const float* w6 = (const float*)d_in[7];
    const int* lidx = (const int*)d_in[8];
    const int* ridx = (const int*)d_in[9];
    float* out = (float*)d_out;

    int prep_work = NROWS * K_ + CHW_ * B_ + K_ * 64;   // 61472
    prep_kernel<<<(prep_work + 255) / 256, 256>>>(x, w0, w1, w2, w3, w4, w5, w6,
                                                  lidx, ridx);
    logic_kernel<<<dim3(P_ / TP, K_), 128>>>(out);
}

// round 15
// speedup vs baseline: 1.1875x; 1.0283x over previous
#include <cuda_runtime.h>
#include <cuda_fp16.h>

// LogicConv3d: B=16, C=3, H=W=32, K=64, P=784, S=64, 7-level soft logic tree.
// d_in: [0]=x f32[16,3,32,32], [1..7]=w0..w6 f32[2^(6-l),64,16],
//       [8]=left_idx i32[64,784,64,3], [9]=right_idx i32[64,784,64,3]
// d_out: f32[16,64,784,1]
//
// idx(k,p,s) = idx(k,0,s) + patch_shift(p); only the p=0 slice is read.

#define B_ 16
#define C_ 3
#define HW_ 1024
#define CHW_ 3072
#define K_ 64
#define P_ 784
#define KP_ (K_ * P_)     // 50176
#define NROWS 127
#define TP 16             // patches per block (784 = 49*16)

// scratch
__device__ float4 g_coef[K_ * NROWS];     // per-(k,node) gate coeffs (fp32)
__device__ uint4  g_coefh[K_ * NROWS];    // same, splatted half2 {c0c0,c1c1,c2c2,c3c3}
__device__ __half g_xth[CHW_ * B_];       // x transposed fp16: [row][batch] (96KB)
__device__ int2   g_off0[K_ * 64];        // p=0 (left,right) BYTE offsets per (k,s)

__constant__ float G4[16][4] = {
    {0,0,0,0},{0,0,0,1},{0,1,0,-1},{0,1,0,0},
    {0,0,1,-1},{0,0,1,0},{0,1,1,-2},{0,1,1,-1},
    {1,-1,-1,1},{1,-1,-1,2},{1,0,-1,0},{1,0,-1,1},
    {1,-1,0,0},{1,-1,0,1},{1,0,0,-1},{1,0,0,0}};

// ---------------------------------------------------------------------------
// Prep (tiny): softmax coeffs + fp16 x transpose + p=0 offset extraction.
// ---------------------------------------------------------------------------
__global__ void prep_kernel(const float* __restrict__ x,
                            const float* __restrict__ w0, const float* __restrict__ w1,
                            const float* __restrict__ w2, const float* __restrict__ w3,
                            const float* __restrict__ w4, const float* __restrict__ w5,
                            const float* __restrict__ w6,
                            const int* __restrict__ lidx,
                            const int* __restrict__ ridx) {
    int r = blockIdx.x * 256 + threadIdx.x;
    if (r < NROWS * K_) {
        int row = r >> 6;
        int k   = r & 63;
        int bse = 0, n = 64, l = 0;
        while (row >= bse + n) { bse += n; n >>= 1; ++l; }
        int s = row - bse;
        const float* ws[7] = {w0, w1, w2, w3, w4, w5, w6};
        const float* p = ws[l] + (s * K_ + k) * 16;
        float v[16], m = -1e30f;
#pragma unroll
        for (int i = 0; i < 16; ++i) { v[i] = p[i]; m = fmaxf(m, v[i]); }
        float sum = 0.f, c0 = 0.f, c1 = 0.f, c2 = 0.f, c3 = 0.f;
#pragma unroll
        for (int i = 0; i < 16; ++i) {
            float e = expf(v[i] - m);
            sum += e;
            c0 += e * G4[i][0]; c1 += e * G4[i][1];
            c2 += e * G4[i][2]; c3 += e * G4[i][3];
        }
        float inv = 1.f / sum;
        c0 *= inv; c1 *= inv; c2 *= inv; c3 *= inv;
        g_coef[k * NROWS + row] = make_float4(c0, c1, c2, c3);
        union { __half2 h[4]; uint4 u; } cv;
        cv.h[0] = __float2half2_rn(c0); cv.h[1] = __float2half2_rn(c1);
        cv.h[2] = __float2half2_rn(c2); cv.h[3] = __float2half2_rn(c3);
        g_coefh[k * NROWS + row] = cv.u;
        return;
    }
    r -= NROWS * K_;
    if (r < CHW_ * B_) {
        int b = r & 15, off = r >> 4;
        g_xth[r] = __float2half(x[b * CHW_ + off]);
        return;
    }
    r -= CHW_ * B_;
    if (r < K_ * 64) {
        int k = r >> 6;
        int s = r & 63;
        long base = ((long)k * P_ * 64 + s) * 3;     // the p = 0 slice
        int h = lidx[base], w = lidx[base + 1], c = lidx[base + 2];
        int lo = (c * HW_ + h * 32 + w) << 5;        // byte offset into fp16 xt
        h = ridx[base]; w = ridx[base + 1]; c = ridx[base + 2];
        int ro = (c * HW_ + h * 32 + w) << 5;
        g_off0[r] = make_int2(lo, ro);
    }
}

// ---------------------------------------------------------------------------
// Main kernel: 64 threads = 4 batch-quads x 16 patches, one k.
// Each thread carries 4 batches (h2x2, LDG.64 gathers). The per-warp LDS
// overhead (64 offset + 127 coeff broadcasts) is amortized over 128 values.
// Depth-first tree (st[5], 10 regs) for levels 0-4 in HFMA2; levels 5-6 fp32.
// Patch shift folded into the gather base pointer; no idx stream.
// ---------------------------------------------------------------------------
struct h2x2 { __half2 a, b; };

__device__ __forceinline__ h2x2 hgate2(h2x2 A, h2x2 B, uint4 cw) {
    const __half2* c = (const __half2*)&cw;
    h2x2 r;
    r.a = __hfma2(B.a, __hfma2(c[3], A.a, c[2]), __hfma2(c[1], A.a, c[0]));
    r.b = __hfma2(B.b, __hfma2(c[3], A.b, c[2]), __hfma2(c[1], A.b, c[0]));
    return r;
}

__device__ __forceinline__ float2 gate2(float2 a, float2 b, float4 c) {
    float2 r;
    r.x = fmaf(b.x, fmaf(c.w, a.x, c.z), fmaf(c.y, a.x, c.x));
    r.y = fmaf(b.y, fmaf(c.w, a.y, c.z), fmaf(c.y, a.y, c.x));
    return r;
}

__global__ __launch_bounds__(64, 20)
void logic_kernel(float* __restrict__ out) {
    __shared__ uint4 scoefh[NROWS];    // half2-splatted coeffs, 16B/node
    __shared__ int2  soff0[64];        // p=0 (left,right) byte offsets (broadcast)

    const int k   = blockIdx.y;
    const int p0  = blockIdx.x * TP;
    const int tid = threadIdx.x;

    if (tid < 64) {
        scoefh[tid] = g_coefh[k * NROWS + tid];
        soff0[tid]  = g_off0[(k << 6) + tid];
    }
    if (tid < NROWS - 64) scoefh[64 + tid] = g_coefh[k * NROWS + 64 + tid];
    __syncthreads();

    const int bg4 = tid & 3;           // batch quad (4 batches = 8B)
    const int pl  = tid >> 2;          // patch lane 0..15 (8 consecutive per warp)
    const int p   = p0 + pl;
    const int ih  = p / 28;
    const int iw  = p - ih * 28;
    const char* xtb = (const char*)g_xth + bg4 * 8 + ih * 1024 + iw * 32;

    float2 lv4a[4], lv4b[4];           // level-4 subtree outputs (fp32)
    h2x2 st[5];
    int sp = 0;
#pragma unroll
    for (int s = 0; s < 64; ++s) {
        int2 o = soff0[s];
        h2x2 A  = *(const h2x2*)(xtb + o.x);
        h2x2 Bv = *(const h2x2*)(xtb + o.y);
        h2x2 v = hgate2(A, Bv, scoefh[s]);
#pragma unroll
        for (int l = 1; l <= 4; ++l) {
            if (((s + 1) & ((1 << l) - 1)) == 0) {
                v = hgate2(st[--sp], v, scoefh[(128 - (128 >> l)) + (s >> l)]);
            }
        }
        if (((s + 1) & 15) == 0) {     // group complete -> fp32
            int g = s >> 4;
            lv4a[g] = __half22float2(v.a);
            lv4b[g] = __half22float2(v.b);
        } else {
            st[sp++] = v;
        }
    }

    // last two levels in fp32 (coeffs uniform across block -> cached LDG)
    const float4* gcf = g_coef + k * NROWS;
    float4 c5a = gcf[124], c5b = gcf[125], c6 = gcf[126];
    float2 ta = gate2(gate2(lv4a[0], lv4a[1], c5a), gate2(lv4a[2], lv4a[3], c5b), c6);
    float2 tb = gate2(gate2(lv4b[0], lv4b[1], c5a), gate2(lv4b[2], lv4b[3], c5b), c6);

    long ob0 = (long)(bg4 * 4) * KP_ + k * P_ + p;
    out[ob0]           = ta.x;
    out[ob0 + KP_]     = ta.y;
    out[ob0 + 2 * KP_] = tb.x;
    out[ob0 + 3 * KP_] = tb.y;
}

// ---------------------------------------------------------------------------
extern "C" void kernel_launch(void* const* d_in, const int* in_sizes, int n_in,
                              void* d_out, int out_size) {
    const float* x  = (const float*)d_in[0];
    const float* w0 = (const float*)d_in[1];
    const float* w1 = (const float*)d_in[2];
    const float* w2 = (const float*)d_in[3];
    const float* w3 = (const float*)d_in[4];
    const float* w4 = (const float*)d_in[5];
    const float* w5 = (const float*)d_in[6];
    const float* w6 = (const float*)d_in[7];
    const int* lidx = (const int*)d_in[8];
    const int* ridx = (const int*)d_in[9];
    float* out = (float*)d_out;

    int prep_work = NROWS * K_ + CHW_ * B_ + K_ * 64;   // 61472
    prep_kernel<<<(prep_work + 255) / 256, 256>>>(x, w0, w1, w2, w3, w4, w5, w6,
                                                  lidx, ridx);
    logic_kernel<<<dim3(P_ / TP, K_), 64>>>(out);
}

// round 16
// speedup vs baseline: 1.5895x; 1.3386x over previous
#include <cuda_runtime.h>
#include <cuda_fp16.h>

// LogicConv3d: B=16, C=3, H=W=32, K=64, P=784, S=64, 7-level soft logic tree.
// d_in: [0]=x f32[16,3,32,32], [1..7]=w0..w6 f32[2^(6-l),64,16],
//       [8]=left_idx i32[64,784,64,3], [9]=right_idx i32[64,784,64,3]
// d_out: f32[16,64,784,1]
//
// idx(k,p,s) = idx(k,0,s) + patch_shift(p); only the p=0 slice is read.

#define B_ 16
#define C_ 3
#define HW_ 1024
#define CHW_ 3072
#define K_ 64
#define P_ 784
#define KP_ (K_ * P_)     // 50176
#define NROWS 127
#define TP 16             // patches per warp (784 = 49*16)

// scratch
__device__ float4 g_coef[K_ * NROWS];     // per-(k,node) gate coeffs (fp32)
__device__ uint4  g_coefh[K_ * NROWS];    // same, splatted half2 {c0c0,c1c1,c2c2,c3c3}
__device__ __half g_xth[CHW_ * B_];       // x transposed fp16: [row][batch] (96KB)
__device__ int2   g_off0[K_ * 64];        // p=0 (left,right) BYTE offsets per (k,s)

__constant__ float G4[16][4] = {
    {0,0,0,0},{0,0,0,1},{0,1,0,-1},{0,1,0,0},
    {0,0,1,-1},{0,0,1,0},{0,1,1,-2},{0,1,1,-1},
    {1,-1,-1,1},{1,-1,-1,2},{1,0,-1,0},{1,0,-1,1},
    {1,-1,0,0},{1,-1,0,1},{1,0,0,-1},{1,0,0,0}};

// ---------------------------------------------------------------------------
// Prep (tiny): softmax coeffs + fp16 x transpose + p=0 offset extraction.
// ---------------------------------------------------------------------------
__global__ void prep_kernel(const float* __restrict__ x,
                            const float* __restrict__ w0, const float* __restrict__ w1,
                            const float* __restrict__ w2, const float* __restrict__ w3,
                            const float* __restrict__ w4, const float* __restrict__ w5,
                            const float* __restrict__ w6,
                            const int* __restrict__ lidx,
                            const int* __restrict__ ridx) {
    int r = blockIdx.x * 256 + threadIdx.x;
    if (r < NROWS * K_) {
        int row = r >> 6;
        int k   = r & 63;
        int bse = 0, n = 64, l = 0;
        while (row >= bse + n) { bse += n; n >>= 1; ++l; }
        int s = row - bse;
        const float* ws[7] = {w0, w1, w2, w3, w4, w5, w6};
        const float* p = ws[l] + (s * K_ + k) * 16;
        float v[16], m = -1e30f;
#pragma unroll
        for (int i = 0; i < 16; ++i) { v[i] = p[i]; m = fmaxf(m, v[i]); }
        float sum = 0.f, c0 = 0.f, c1 = 0.f, c2 = 0.f, c3 = 0.f;
#pragma unroll
        for (int i = 0; i < 16; ++i) {
            float e = expf(v[i] - m);
            sum += e;
            c0 += e * G4[i][0]; c1 += e * G4[i][1];
            c2 += e * G4[i][2]; c3 += e * G4[i][3];
        }
        float inv = 1.f / sum;
        c0 *= inv; c1 *= inv; c2 *= inv; c3 *= inv;
        g_coef[k * NROWS + row] = make_float4(c0, c1, c2, c3);
        union { __half2 h[4]; uint4 u; } cv;
        cv.h[0] = __float2half2_rn(c0); cv.h[1] = __float2half2_rn(c1);
        cv.h[2] = __float2half2_rn(c2); cv.h[3] = __float2half2_rn(c3);
        g_coefh[k * NROWS + row] = cv.u;
        return;
    }
    r -= NROWS * K_;
    if (r < CHW_ * B_) {
        int b = r & 15, off = r >> 4;
        g_xth[r] = __float2half(x[b * CHW_ + off]);
        return;
    }
    r -= CHW_ * B_;
    if (r < K_ * 64) {
        int k = r >> 6;
        int s = r & 63;
        long base = ((long)k * P_ * 64 + s) * 3;     // the p = 0 slice
        int h = lidx[base], w = lidx[base + 1], c = lidx[base + 2];
        int lo = (c * HW_ + h * 32 + w) << 5;        // byte offset into fp16 xt
        h = ridx[base]; w = ridx[base + 1]; c = ridx[base + 2];
        int ro = (c * HW_ + h * 32 + w) << 5;
        g_off0[r] = make_int2(lo, ro);
    }
}

// ---------------------------------------------------------------------------
// Main kernel: 64 threads = 2 warps; warp w handles k = 2*blockIdx.y + w.
// Within a warp: 2 batch-octets (8 batches = 16B = LDG.128 gather) x 16
// patches. Per-warp LDS overhead amortized over 256 values. s processed in
// pairs with the level-1 gate fused -> stack depth 3, one soff LDS.128/pair.
// Levels 0-4 HFMA2, levels 5-6 fp32.
// ---------------------------------------------------------------------------
struct h2x4 { __half2 h[4]; };

__device__ __forceinline__ h2x4 hgate4(h2x4 A, h2x4 B, uint4 cw) {
    const __half2* c = (const __half2*)&cw;
    h2x4 r;
#pragma unroll
    for (int j = 0; j < 4; ++j)
        r.h[j] = __hfma2(B.h[j], __hfma2(c[3], A.h[j], c[2]),
                                  __hfma2(c[1], A.h[j], c[0]));
    return r;
}

__device__ __forceinline__ float2 gate2(float2 a, float2 b, float4 c) {
    float2 r;
    r.x = fmaf(b.x, fmaf(c.w, a.x, c.z), fmaf(c.y, a.x, c.x));
    r.y = fmaf(b.y, fmaf(c.w, a.y, c.z), fmaf(c.y, a.y, c.x));
    return r;
}

__global__ __launch_bounds__(64, 16)
void logic_kernel(float* __restrict__ out) {
    __shared__ uint4 scoefh[2][NROWS]; // per-warp-k half2-splatted coeffs
    __shared__ int2  soff0[2][64];     // per-warp-k p=0 byte offsets

    const int k0  = blockIdx.y * 2;
    const int p0  = blockIdx.x * TP;
    const int tid = threadIdx.x;

    for (int i = tid; i < 2 * NROWS; i += 64) {
        int kk  = (i < NROWS) ? 0 : 1;
        int idx = (i < NROWS) ? i : i - NROWS;
        scoefh[kk][idx] = g_coefh[(k0 + kk) * NROWS + idx];
    }
    for (int i = tid; i < 128; i += 64)
        soff0[i >> 6][i & 63] = g_off0[((k0 + (i >> 6)) << 6) + (i & 63)];
    __syncthreads();

    const int wp   = tid >> 5;         // warp -> k
    const int k    = k0 + wp;
    const int lane = tid & 31;
    const int bg8  = lane & 1;         // batch octet (8 batches = 16B)
    const int pl   = lane >> 1;        // patch lane 0..15
    const int p    = p0 + pl;
    const int ih   = p / 28;
    const int iw   = p - ih * 28;
    const char* xtb = (const char*)g_xth + bg8 * 16 + ih * 1024 + iw * 32;

    const uint4* mycoef = scoefh[wp];
    const int2*  myoff  = soff0[wp];

    __half2 lv4h[4][4];                // [group][j] level-4 outputs (half2)
    h2x4 st[3];
    int sp = 0;
#pragma unroll
    for (int s2 = 0; s2 < 32; ++s2) {
        const int s = s2 << 1;
        int4 oo = *(const int4*)&myoff[s];     // (l0,r0,l1,r1)
        uint4 a0 = *(const uint4*)(xtb + oo.x);
        uint4 b0 = *(const uint4*)(xtb + oo.y);
        uint4 a1 = *(const uint4*)(xtb + oo.z);
        uint4 b1 = *(const uint4*)(xtb + oo.w);
        h2x4 v0 = hgate4(*(h2x4*)&a0, *(h2x4*)&b0, mycoef[s]);
        h2x4 v1 = hgate4(*(h2x4*)&a1, *(h2x4*)&b1, mycoef[s + 1]);
        // fused level-1 gate: node 64 + s2
        h2x4 v = hgate4(v0, v1, mycoef[64 + s2]);
        if (((s2 + 1) & 1) == 0) v = hgate4(st[--sp], v, mycoef[96  + (s2 >> 1)]);
        if (((s2 + 1) & 3) == 0) v = hgate4(st[--sp], v, mycoef[112 + (s2 >> 2)]);
        if (((s2 + 1) & 7) == 0) {
            v = hgate4(st[--sp], v, mycoef[120 + (s2 >> 3)]);   // level 4: group root
            const int g = s2 >> 3;
#pragma unroll
            for (int j = 0; j < 4; ++j) lv4h[g][j] = v.h[j];
        } else {
            st[sp++] = v;
        }
    }

    // last two levels in fp32 (coeffs uniform across warp -> cached LDG)
    const float4* gcf = g_coef + k * NROWS;
    float4 c5a = gcf[124], c5b = gcf[125], c6 = gcf[126];
    long obase = (long)(bg8 * 8) * KP_ + k * P_ + p;
#pragma unroll
    for (int j = 0; j < 4; ++j) {
        float2 x0 = __half22float2(lv4h[0][j]);
        float2 x1 = __half22float2(lv4h[1][j]);
        float2 x2 = __half22float2(lv4h[2][j]);
        float2 x3 = __half22float2(lv4h[3][j]);
        float2 r = gate2(gate2(x0, x1, c5a), gate2(x2, x3, c5b), c6);
        out[obase + (long)(2 * j) * KP_]     = r.x;
        out[obase + (long)(2 * j + 1) * KP_] = r.y;
    }
}

// ---------------------------------------------------------------------------
extern "C" void kernel_launch(void* const* d_in, const int* in_sizes, int n_in,
                              void* d_out, int out_size) {
    const float* x  = (const float*)d_in[0];
    const float* w0 = (const float*)d_in[1];
    const float* w1 = (const float*)d_in[2];
    const float* w2 = (const float*)d_in[3];
    const float* w3 = (const float*)d_in[4];
    const float* w4 = (const float*)d_in[5];
    const float* w5 = (const float*)d_in[6];
    const float* w6 = (const float*)d_in[7];
    const int* lidx = (const int*)d_in[8];
    const int* ridx = (const int*)d_in[9];
    float* out = (float*)d_out;

    int prep_work = NROWS * K_ + CHW_ * B_ + K_ * 64;   // 61472
    prep_kernel<<<(prep_work + 255) / 256, 256>>>(x, w0, w1, w2, w3, w4, w5, w6,
                                                  lidx, ridx);
    logic_kernel<<<dim3(P_ / TP, K_ / 2), 64>>>(out);
}

// round 17
// speedup vs baseline: 1.7007x; 1.0699x over previous
#include <cuda_runtime.h>
#include <cuda_fp16.h>

// LogicConv3d: B=16, C=3, H=W=32, K=64, P=784, S=64, 7-level soft logic tree.
// idx(k,p,s) = idx(k,0,s) + patch_shift(p); only the p=0 idx slice is read.

#define B_ 16
#define C_ 3
#define HW_ 1024
#define CHW_ 3072
#define K_ 64
#define P_ 784
#define KP_ (K_ * P_)     // 50176
#define NROWS 127
#define TP 16             // patches per warp-pair

// scratch
__device__ float4 g_coef[K_ * NROWS];     // per-(k,node) gate coeffs (fp32)
__device__ uint4  g_coefh[K_ * NROWS];    // same, splatted half2 {c0c0,c1c1,c2c2,c3c3}
__device__ __half g_xth[CHW_ * B_];       // x transposed fp16: [row][batch] (96KB)
__device__ int2   g_off0[K_ * 64];        // p=0 (left,right) BYTE offsets per (k,s)

__constant__ float G4[16][4] = {
    {0,0,0,0},{0,0,0,1},{0,1,0,-1},{0,1,0,0},
    {0,0,1,-1},{0,0,1,0},{0,1,1,-2},{0,1,1,-1},
    {1,-1,-1,1},{1,-1,-1,2},{1,0,-1,0},{1,0,-1,1},
    {1,-1,0,0},{1,-1,0,1},{1,0,0,-1},{1,0,0,0}};

// ---------------------------------------------------------------------------
// Prep (tiny): softmax coeffs + fp16 x transpose + p=0 offset extraction.
// ---------------------------------------------------------------------------
__global__ void prep_kernel(const float* __restrict__ x,
                            const float* __restrict__ w0, const float* __restrict__ w1,
                            const float* __restrict__ w2, const float* __restrict__ w3,
                            const float* __restrict__ w4, const float* __restrict__ w5,
                            const float* __restrict__ w6,
                            const int* __restrict__ lidx,
                            const int* __restrict__ ridx) {
    int r = blockIdx.x * 256 + threadIdx.x;
    if (r < NROWS * K_) {
        int row = r >> 6;
        int k   = r & 63;
        int bse = 0, n = 64, l = 0;
        while (row >= bse + n) { bse += n; n >>= 1; ++l; }
        int s = row - bse;
        const float* ws[7] = {w0, w1, w2, w3, w4, w5, w6};
        const float* p = ws[l] + (s * K_ + k) * 16;
        float v[16], m = -1e30f;
#pragma unroll
        for (int i = 0; i < 16; ++i) { v[i] = p[i]; m = fmaxf(m, v[i]); }
        float sum = 0.f, c0 = 0.f, c1 = 0.f, c2 = 0.f, c3 = 0.f;
#pragma unroll
        for (int i = 0; i < 16; ++i) {
            float e = expf(v[i] - m);
            sum += e;
            c0 += e * G4[i][0]; c1 += e * G4[i][1];
            c2 += e * G4[i][2]; c3 += e * G4[i][3];
        }
        float inv = 1.f / sum;
        c0 *= inv; c1 *= inv; c2 *= inv; c3 *= inv;
        g_coef[k * NROWS + row] = make_float4(c0, c1, c2, c3);
        union { __half2 h[4]; uint4 u; } cv;
        cv.h[0] = __float2half2_rn(c0); cv.h[1] = __float2half2_rn(c1);
        cv.h[2] = __float2half2_rn(c2); cv.h[3] = __float2half2_rn(c3);
        g_coefh[k * NROWS + row] = cv.u;
        return;
    }
    r -= NROWS * K_;
    if (r < CHW_ * B_) {
        int b = r & 15, off = r >> 4;
        g_xth[r] = __float2half(x[b * CHW_ + off]);
        return;
    }
    r -= CHW_ * B_;
    if (r < K_ * 64) {
        int k = r >> 6;
        int s = r & 63;
        long base = ((long)k * P_ * 64 + s) * 3;     // the p = 0 slice
        int h = lidx[base], w = lidx[base + 1], c = lidx[base + 2];
        int lo = (c * HW_ + h * 32 + w) << 5;        // byte offset into fp16 xt
        h = ridx[base]; w = ridx[base + 1]; c = ridx[base + 2];
        int ro = (c * HW_ + h * 32 + w) << 5;
        g_off0[r] = make_int2(lo, ro);
    }
}

// ---------------------------------------------------------------------------
// Main kernel: 128 threads = 4 warps = 2 k's x 2 tree-halves.
// Each warp: 2 batch-octets (LDG.128) x 16 patches, 32 leaves -> its
// level-5 node. Half 1 ships its fp32 t5 through SMEM; half 0 applies the
// root gate and stores. Doubles warp-level parallelism at constant work.
// Levels 0-4 HFMA2 (pair-fused level 1), levels 5-6 fp32.
// ---------------------------------------------------------------------------
struct h2x4 { __half2 h[4]; };

__device__ __forceinline__ h2x4 hgate4(h2x4 A, h2x4 B, uint4 cw) {
    const __half2* c = (const __half2*)&cw;
    h2x4 r;
#pragma unroll
    for (int j = 0; j < 4; ++j)
        r.h[j] = __hfma2(B.h[j], __hfma2(c[3], A.h[j], c[2]),
                                  __hfma2(c[1], A.h[j], c[0]));
    return r;
}

__device__ __forceinline__ float2 gate2(float2 a, float2 b, float4 c) {
    float2 r;
    r.x = fmaf(b.x, fmaf(c.w, a.x, c.z), fmaf(c.y, a.x, c.x));
    r.y = fmaf(b.y, fmaf(c.w, a.y, c.z), fmaf(c.y, a.y, c.x));
    return r;
}

__global__ __launch_bounds__(128, 8)
void logic_kernel(float* __restrict__ out) {
    __shared__ uint4  scoefh[2][NROWS];   // per-k half2-splatted coeffs
    __shared__ int2   soff0[2][64];       // per-k p=0 byte offsets
    __shared__ float4 xbuf[2][32][2];     // t5b exchange: [kk][lane][32B]

    const int k0  = blockIdx.y * 2;
    const int p0  = blockIdx.x * TP;
    const int tid = threadIdx.x;

    for (int i = tid; i < 2 * NROWS; i += 128) {
        int kk  = (i < NROWS) ? 0 : 1;
        int idx = (i < NROWS) ? i : i - NROWS;
        scoefh[kk][idx] = g_coefh[(k0 + kk) * NROWS + idx];
    }
    if (tid < 128) soff0[tid >> 6][tid & 63] = g_off0[((k0 + (tid >> 6)) << 6) + (tid & 63)];
    __syncthreads();

    const int wp   = tid >> 5;
    const int half = wp & 1;           // tree half (groups 0,1 vs 2,3)
    const int kk   = wp >> 1;
    const int k    = k0 + kk;
    const int lane = tid & 31;
    const int bg8  = lane & 1;         // batch octet (8 batches = 16B)
    const int pl   = lane >> 1;        // patch lane 0..15
    const int p    = p0 + pl;
    const int ih   = p / 28;
    const int iw   = p - ih * 28;
    const char* xtb = (const char*)g_xth + bg8 * 16 + ih * 1024 + iw * 32;

    const uint4* mycoef = scoefh[kk];
    const int2*  myoff  = soff0[kk];
    const int sbase = half << 5;       // this warp's 32-leaf range

    __half2 lv4h[2][4];                // [local group][j] level-4 outputs
    h2x4 st[3];
    int sp = 0;
#pragma unroll
    for (int s2 = 0; s2 < 16; ++s2) {
        const int s = sbase + (s2 << 1);
        int4 oo = *(const int4*)&myoff[s];     // (l0,r0,l1,r1)
        uint4 a0 = *(const uint4*)(xtb + oo.x);
        uint4 b0 = *(const uint4*)(xtb + oo.y);
        uint4 a1 = *(const uint4*)(xtb + oo.z);
        uint4 b1 = *(const uint4*)(xtb + oo.w);
        h2x4 v0 = hgate4(*(h2x4*)&a0, *(h2x4*)&b0, mycoef[s]);
        h2x4 v1 = hgate4(*(h2x4*)&a1, *(h2x4*)&b1, mycoef[s + 1]);
        h2x4 v  = hgate4(v0, v1, mycoef[64 + (s >> 1)]);        // fused level 1
        if ((s2 & 1) == 1) v = hgate4(st[--sp], v, mycoef[96  + (s >> 2)]);
        if ((s2 & 3) == 3) v = hgate4(st[--sp], v, mycoef[112 + (s >> 3)]);
        if ((s2 & 7) == 7) {
            v = hgate4(st[--sp], v, mycoef[120 + (s >> 4)]);    // level-4 group root
            const int g = s2 >> 3;     // local group 0/1
#pragma unroll
            for (int j = 0; j < 4; ++j) lv4h[g][j] = v.h[j];
        } else {
            st[sp++] = v;
        }
    }

    // level 5 in fp32 (node 124 for half 0, 125 for half 1)
    const float4* gcf = g_coef + k * NROWS;
    float4 c5 = gcf[124 + half];
    float2 t5[4];
#pragma unroll
    for (int j = 0; j < 4; ++j)
        t5[j] = gate2(__half22float2(lv4h[0][j]), __half22float2(lv4h[1][j]), c5);

    if (half == 1) {
        xbuf[kk][lane][0] = make_float4(t5[0].x, t5[0].y, t5[1].x, t5[1].y);
        xbuf[kk][lane][1] = make_float4(t5[2].x, t5[2].y, t5[3].x, t5[3].y);
    }
    __syncthreads();

    if (half == 0) {
        float4 q0 = xbuf[kk][lane][0];
        float4 q1 = xbuf[kk][lane][1];
        float2 t5b[4] = {{q0.x, q0.y}, {q0.z, q0.w}, {q1.x, q1.y}, {q1.z, q1.w}};
        float4 c6 = gcf[126];
        long obase = (long)(bg8 * 8) * KP_ + k * P_ + p;
#pragma unroll
        for (int j = 0; j < 4; ++j) {
            float2 r = gate2(t5[j], t5b[j], c6);
            out[obase + (long)(2 * j) * KP_]     = r.x;
            out[obase + (long)(2 * j + 1) * KP_] = r.y;
        }
    }
}

// ---------------------------------------------------------------------------
extern "C" void kernel_launch(void* const* d_in, const int* in_sizes, int n_in,
                              void* d_out, int out_size) {
    const float* x  = (const float*)d_in[0];
    const float* w0 = (const float*)d_in[1];
    const float* w1 = (const float*)d_in[2];
    const float* w2 = (const float*)d_in[3];
    const float* w3 = (const float*)d_in[4];
    const float* w4 = (const float*)d_in[5];
    const float* w5 = (const float*)d_in[6];
    const float* w6 = (const float*)d_in[7];
    const int* lidx = (const int*)d_in[8];
    const int* ridx = (const int*)d_in[9];
    float* out = (float*)d_out;

    int prep_work = NROWS * K_ + CHW_ * B_ + K_ * 64;   // 61472
    prep_kernel<<<(prep_work + 255) / 256, 256>>>(x, w0, w1, w2, w3, w4, w5, w6,
                                                  lidx, ridx);
    logic_kernel<<<dim3(P_ / TP, K_ / 2), 128>>>(out);
}